// round 4
// baseline (speedup 1.0000x reference)
#include <cuda_runtime.h>
#include <cuda_bf16.h>
#include <math.h>
#include <stdint.h>

#define NPTS 512
#define DDIM 128
#define NMC  64
#define NROWS (3*NMC*NPTS)
#define DENOM 16777216.0
#define NCTA_DIST (4*4*3*NMC)

// Scratch (static device globals — no allocation allowed)
__device__ uint8_t g_Xf8[(size_t)3*NMC*NPTS*DDIM];   // 12.6MB e4m3
__device__ float   g_norm[3*NMC*NPTS];
__device__ double  g_accum;
__device__ unsigned g_count;

__device__ __forceinline__ uint32_t smem_u32(const void* p) {
    uint32_t a;
    asm("{ .reg .u64 t; cvta.to.shared.u64 t, %1; cvt.u32.u64 %0, t; }" : "=r"(a) : "l"(p));
    return a;
}

__device__ __forceinline__ void ldmatrix_x4(uint32_t* r, uint32_t addr) {
    asm volatile("ldmatrix.sync.aligned.m8n8.x4.shared.b16 {%0,%1,%2,%3}, [%4];"
                 : "=r"(r[0]), "=r"(r[1]), "=r"(r[2]), "=r"(r[3]) : "r"(addr));
}

__device__ __forceinline__ void mma_fp8(float* c, const uint32_t* a, const uint32_t* b) {
    asm volatile(
        "mma.sync.aligned.m16n8k32.row.col.f32.e4m3.e4m3.f32 "
        "{%0,%1,%2,%3}, {%4,%5,%6,%7}, {%8,%9}, {%0,%1,%2,%3};"
        : "+f"(c[0]), "+f"(c[1]), "+f"(c[2]), "+f"(c[3])
        : "r"(a[0]), "r"(a[1]), "r"(a[2]), "r"(a[3]), "r"(b[0]), "r"(b[1]));
}

__device__ __forceinline__ uint32_t pack4_e4m3(float x0, float x1, float x2, float x3) {
    uint16_t lo, hi;
    asm("cvt.rn.satfinite.e4m3x2.f32 %0, %1, %2;" : "=h"(lo) : "f"(x1), "f"(x0));
    asm("cvt.rn.satfinite.e4m3x2.f32 %0, %1, %2;" : "=h"(hi) : "f"(x3), "f"(x2));
    return (uint32_t)lo | ((uint32_t)hi << 16);
}

// ---------------- k_gen: x = mu + sigma*eps -> e4m3 X, fp32 ||x||^2 ------
// One warp per sample row. Also zeroes the accumulator/counter (block 0).
__global__ void k_gen(const float* __restrict__ mu, const float* __restrict__ sigma,
                      const float* __restrict__ epsA, const float* __restrict__ epsB,
                      const float* __restrict__ epsC) {
    if (blockIdx.x == 0 && threadIdx.x == 0) { g_accum = 0.0; g_count = 0u; }
    int w = (blockIdx.x * blockDim.x + threadIdx.x) >> 5;
    int lane = threadIdx.x & 31;
    if (w >= NROWS) return;
    int s   = w / (NMC*NPTS);
    int rem = w - s*(NMC*NPTS);
    int m   = rem / NPTS;
    int n   = rem - m*NPTS;
    const float* eps = (s == 0) ? epsA : (s == 1) ? epsB : epsC;
    float4 a = ((const float4*)(mu    + (size_t)(s*NPTS + n)*DDIM))[lane];
    float4 b = ((const float4*)(sigma + (size_t)(s*NPTS + n)*DDIM))[lane];
    float4 e = ((const float4*)(eps   + ((size_t)m*NPTS + n)*DDIM))[lane];
    float4 x;
    x.x = fmaf(b.x, e.x, a.x);
    x.y = fmaf(b.y, e.y, a.y);
    x.z = fmaf(b.z, e.z, a.z);
    x.w = fmaf(b.w, e.w, a.w);
    ((uint32_t*)(g_Xf8 + (size_t)w*DDIM))[lane] = pack4_e4m3(x.x, x.y, x.z, x.w);
    float ss = x.x*x.x + x.y*x.y + x.z*x.z + x.w*x.w;
    #pragma unroll
    for (int o = 16; o; o >>= 1) ss += __shfl_xor_sync(0xffffffffu, ss, o);
    if (lane == 0) g_norm[w] = ss;
}

// SMEM layout (dynamic):
//   [0:512)        xn[128]
//   [512:1024)     yn[128]
//   [1024:17408)   A tile (128 rows x 128B, XOR-swizzled 16B chunks)
//   [17408:33792)  B tile
#define SM_XN 0
#define SM_YN 512
#define SM_A  1024
#define SM_B  17408
#define SM_TOTAL 33792

// TN fp8 warp-MMA Gram GEMM + fused distance-loss epilogue + last-CTA output.
// blockIdx.z = m*3 + pair; pair 0=(A,C) pos, 1=(B,A) neg, 2=(B,C) neg.
__global__ __launch_bounds__(256) void k_dist(float* __restrict__ out) {
    extern __shared__ char smem[];
    uint32_t sb = smem_u32(smem);
    int tid  = threadIdx.x;
    int lane = tid & 31;
    int w    = tid >> 5;
    int warp_m = w & 3;     // 4 warps over M (32 rows each)
    int warp_n = w >> 2;    // 2 warps over N (64 cols each)

    int p = blockIdx.z % 3;
    int m = blockIdx.z / 3;
    int rs = (p == 0) ? 0 : 1;
    int cs = (p == 0) ? 2 : ((p == 1) ? 0 : 2);

    const uint8_t* Xg = g_Xf8 + (size_t)(rs*NMC + m) * NPTS * DDIM;
    const uint8_t* Yg = g_Xf8 + (size_t)(cs*NMC + m) * NPTS * DDIM;
    const float* nX = g_norm + (size_t)(rs*NMC + m) * NPTS;
    const float* nY = g_norm + (size_t)(cs*NMC + m) * NPTS;
    int row0 = blockIdx.y * 128;
    int col0 = blockIdx.x * 128;

    if (tid < 128) {
        ((float*)(smem + SM_XN))[tid] = nX[row0 + tid];
        ((float*)(smem + SM_YN))[tid] = nY[col0 + tid];
    }

    // Load A/B 128x128 fp8 tiles: 8 chunks of 16B per row, swizzle c^=(row&7).
    {
        const uint4* A16 = (const uint4*)(Xg + (size_t)row0 * DDIM);
        const uint4* B16 = (const uint4*)(Yg + (size_t)col0 * DDIM);
        #pragma unroll
        for (int it = 0; it < 4; it++) {
            int f   = it * 256 + tid;        // 1024 chunks per tile
            int row = f >> 3;
            int c   = f & 7;
            uint32_t dst = (uint32_t)(row * 128 + ((c ^ (row & 7)) << 4));
            *(uint4*)(smem + SM_A + dst) = A16[row * 8 + c];
            *(uint4*)(smem + SM_B + dst) = B16[row * 8 + c];
        }
    }
    __syncthreads();

    float acc[2][8][4];
    #pragma unroll
    for (int mt = 0; mt < 2; mt++)
        #pragma unroll
        for (int nt = 0; nt < 8; nt++)
            #pragma unroll
            for (int r = 0; r < 4; r++) acc[mt][nt][r] = 0.0f;

    // 4 k-steps of k32 fp8. Fragment layouts == bf16 k16 with b16 -> 2 fp8.
    #pragma unroll
    for (int ks = 0; ks < 4; ks++) {
        uint32_t a[2][4];
        #pragma unroll
        for (int mt = 0; mt < 2; mt++) {
            int r  = warp_m * 32 + mt * 16 + (lane & 15);
            int kb = ks * 32 + (lane >> 4) * 16;           // byte offset in row
            uint32_t addr = sb + SM_A + (uint32_t)(r * 128 + (((kb >> 4) ^ (r & 7)) << 4));
            ldmatrix_x4(a[mt], addr);
        }
        uint32_t b[8][2];
        #pragma unroll
        for (int nt2 = 0; nt2 < 4; nt2++) {
            int r  = warp_n * 64 + nt2 * 16 + (lane & 7) + ((lane >> 4) << 3);
            int kb = ks * 32 + ((lane >> 3) & 1) * 16;
            uint32_t addr = sb + SM_B + (uint32_t)(r * 128 + (((kb >> 4) ^ (r & 7)) << 4));
            uint32_t t[4];
            ldmatrix_x4(t, addr);
            b[nt2*2][0]   = t[0]; b[nt2*2][1]   = t[1];
            b[nt2*2+1][0] = t[2]; b[nt2*2+1][1] = t[3];
        }
        #pragma unroll
        for (int mt = 0; mt < 2; mt++)
            #pragma unroll
            for (int nt = 0; nt < 8; nt++)
                mma_fp8(acc[mt][nt], a[mt], b[nt]);
    }

    // Epilogue: fragment (mt,nt) reg r -> m = warp_m*32+mt*16+(lane/4)+(r>=2?8:0),
    //                                     n = warp_n*64+nt*8+(lane%4)*2+(r&1)
    const float* xns = (const float*)(smem + SM_XN);
    const float* yns = (const float*)(smem + SM_YN);
    float local = 0.0f;
    #pragma unroll
    for (int mt = 0; mt < 2; mt++) {
        int mbase = warp_m * 32 + mt * 16 + (lane >> 2);
        float xn0 = xns[mbase];
        float xn1 = xns[mbase + 8];
        #pragma unroll
        for (int nt = 0; nt < 8; nt++) {
            int nbase = warp_n * 64 + nt * 8 + (lane & 3) * 2;
            float yn0 = yns[nbase];
            float yn1 = yns[nbase + 1];
            float d2_00 = xn0 + yn0 - 2.0f * acc[mt][nt][0];
            float d2_01 = xn0 + yn1 - 2.0f * acc[mt][nt][1];
            float d2_10 = xn1 + yn0 - 2.0f * acc[mt][nt][2];
            float d2_11 = xn1 + yn1 - 2.0f * acc[mt][nt][3];
            if (p == 0) {
                local += fmaxf(d2_00, 1e-12f) + fmaxf(d2_01, 1e-12f)
                       + fmaxf(d2_10, 1e-12f) + fmaxf(d2_11, 1e-12f);
            } else {
                if (d2_00 < 4.0f) { float t = 2.0f - sqrtf(fmaxf(d2_00, 1e-12f)); local += t*t; }
                if (d2_01 < 4.0f) { float t = 2.0f - sqrtf(fmaxf(d2_01, 1e-12f)); local += t*t; }
                if (d2_10 < 4.0f) { float t = 2.0f - sqrtf(fmaxf(d2_10, 1e-12f)); local += t*t; }
                if (d2_11 < 4.0f) { float t = 2.0f - sqrtf(fmaxf(d2_11, 1e-12f)); local += t*t; }
            }
        }
    }

    // Reduce: warp -> block -> one double atomic; last CTA writes output.
    #pragma unroll
    for (int o = 16; o; o >>= 1) local += __shfl_xor_sync(0xffffffffu, local, o);
    __shared__ float red[8];
    if (lane == 0) red[w] = local;
    __syncthreads();
    if (tid == 0) {
        float v = red[0] + red[1] + red[2] + red[3]
                + red[4] + red[5] + red[6] + red[7];
        atomicAdd(&g_accum, (double)v);
        __threadfence();
        unsigned t = atomicAdd(&g_count, 1u);
        if (t == NCTA_DIST - 1) {
            double total = atomicAdd(&g_accum, 0.0);   // coherent read
            out[0] = (float)(total * (1.0 / DENOM));
        }
    }
}

extern "C" void kernel_launch(void* const* d_in, const int* in_sizes, int n_in,
                              void* d_out, int out_size) {
    const float* mu    = (const float*)d_in[0];
    const float* sigma = (const float*)d_in[1];
    const float* epsA  = (const float*)d_in[2];
    const float* epsB  = (const float*)d_in[3];
    const float* epsC  = (const float*)d_in[4];
    (void)in_sizes; (void)n_in; (void)out_size;

    cudaFuncSetAttribute(k_dist, cudaFuncAttributeMaxDynamicSharedMemorySize, SM_TOTAL);

    k_gen<<<(NROWS * 32) / 256, 256>>>(mu, sigma, epsA, epsB, epsC);
    dim3 grid(4, 4, 3 * NMC);
    k_dist<<<grid, 256, SM_TOTAL>>>((float*)d_out);
}

// round 5
// speedup vs baseline: 1.4967x; 1.4967x over previous
#include <cuda_runtime.h>
#include <cuda_bf16.h>
#include <math.h>
#include <stdint.h>

#define NPTS 512
#define DDIM 128
#define NMC  64
#define NROWS (3*NMC*NPTS)
#define DENOM 16777216.0
#define NCTA_DIST (4*4*3*NMC)

// Scratch (static device globals — no allocation allowed)
__device__ uint8_t g_Xf8[(size_t)3*NMC*NPTS*DDIM];   // 12.6MB e4m3
__device__ float   g_norm[3*NMC*NPTS];
__device__ double  g_accum;
__device__ unsigned g_count;

__device__ __forceinline__ uint32_t smem_u32(const void* p) {
    uint32_t a;
    asm("{ .reg .u64 t; cvta.to.shared.u64 t, %1; cvt.u32.u64 %0, t; }" : "=r"(a) : "l"(p));
    return a;
}

__device__ __forceinline__ void ldmatrix_x4(uint32_t* r, uint32_t addr) {
    asm volatile("ldmatrix.sync.aligned.m8n8.x4.shared.b16 {%0,%1,%2,%3}, [%4];"
                 : "=r"(r[0]), "=r"(r[1]), "=r"(r[2]), "=r"(r[3]) : "r"(addr));
}

__device__ __forceinline__ void mma_fp8(float* c, const uint32_t* a, const uint32_t* b) {
    asm volatile(
        "mma.sync.aligned.m16n8k32.row.col.f32.e4m3.e4m3.f32 "
        "{%0,%1,%2,%3}, {%4,%5,%6,%7}, {%8,%9}, {%0,%1,%2,%3};"
        : "+f"(c[0]), "+f"(c[1]), "+f"(c[2]), "+f"(c[3])
        : "r"(a[0]), "r"(a[1]), "r"(a[2]), "r"(a[3]), "r"(b[0]), "r"(b[1]));
}

__device__ __forceinline__ uint32_t pack4_e4m3(float x0, float x1, float x2, float x3) {
    uint16_t lo, hi;
    asm("cvt.rn.satfinite.e4m3x2.f32 %0, %1, %2;" : "=h"(lo) : "f"(x1), "f"(x0));
    asm("cvt.rn.satfinite.e4m3x2.f32 %0, %1, %2;" : "=h"(hi) : "f"(x3), "f"(x2));
    return (uint32_t)lo | ((uint32_t)hi << 16);
}

// ---------------- k_gen: x = mu + sigma*eps -> e4m3 X, fp32 ||x||^2 ------
__global__ void k_gen(const float* __restrict__ mu, const float* __restrict__ sigma,
                      const float* __restrict__ epsA, const float* __restrict__ epsB,
                      const float* __restrict__ epsC) {
    if (blockIdx.x == 0 && threadIdx.x == 0) { g_accum = 0.0; g_count = 0u; }
    int w = (blockIdx.x * blockDim.x + threadIdx.x) >> 5;
    int lane = threadIdx.x & 31;
    if (w >= NROWS) return;
    int s   = w / (NMC*NPTS);
    int rem = w - s*(NMC*NPTS);
    int m   = rem / NPTS;
    int n   = rem - m*NPTS;
    const float* eps = (s == 0) ? epsA : (s == 1) ? epsB : epsC;
    float4 a = ((const float4*)(mu    + (size_t)(s*NPTS + n)*DDIM))[lane];
    float4 b = ((const float4*)(sigma + (size_t)(s*NPTS + n)*DDIM))[lane];
    float4 e = ((const float4*)(eps   + ((size_t)m*NPTS + n)*DDIM))[lane];
    float4 x;
    x.x = fmaf(b.x, e.x, a.x);
    x.y = fmaf(b.y, e.y, a.y);
    x.z = fmaf(b.z, e.z, a.z);
    x.w = fmaf(b.w, e.w, a.w);
    ((uint32_t*)(g_Xf8 + (size_t)w*DDIM))[lane] = pack4_e4m3(x.x, x.y, x.z, x.w);
    float ss = x.x*x.x + x.y*x.y + x.z*x.z + x.w*x.w;
    #pragma unroll
    for (int o = 16; o; o >>= 1) ss += __shfl_xor_sync(0xffffffffu, ss, o);
    if (lane == 0) g_norm[w] = ss;
}

// SMEM layout (dynamic):
//   [0:512)        xn[128]
//   [512:1024)     yn[128]
//   [1024:17408)   A tile (128 rows x 128B, XOR-swizzled 16B chunks)
//   [17408:33792)  B tile
#define SM_XN 0
#define SM_YN 512
#define SM_A  1024
#define SM_B  17408
#define SM_TOTAL 33792

// TN fp8 warp-MMA Gram GEMM + fused distance-loss epilogue + last-CTA output.
// 2 CTAs/SM enforced: <=128 regs.
__global__ __launch_bounds__(256, 2) void k_dist(float* __restrict__ out) {
    extern __shared__ char smem[];
    uint32_t sb = smem_u32(smem);
    int tid  = threadIdx.x;
    int lane = tid & 31;
    int w    = tid >> 5;
    int warp_m = w & 3;     // 4 warps over M (32 rows each)
    int warp_n = w >> 2;    // 2 warps over N (64 cols each)

    int p = blockIdx.z % 3;
    int m = blockIdx.z / 3;
    int rs = (p == 0) ? 0 : 1;
    int cs = (p == 0) ? 2 : ((p == 1) ? 0 : 2);

    const uint8_t* Xg = g_Xf8 + (size_t)(rs*NMC + m) * NPTS * DDIM;
    const uint8_t* Yg = g_Xf8 + (size_t)(cs*NMC + m) * NPTS * DDIM;
    const float* nX = g_norm + (size_t)(rs*NMC + m) * NPTS;
    const float* nY = g_norm + (size_t)(cs*NMC + m) * NPTS;
    int row0 = blockIdx.y * 128;
    int col0 = blockIdx.x * 128;

    if (tid < 128) {
        ((float*)(smem + SM_XN))[tid] = nX[row0 + tid];
        ((float*)(smem + SM_YN))[tid] = nY[col0 + tid];
    }

    // Load A/B 128x128 fp8 tiles: 8 chunks of 16B per row, swizzle c^=(row&7).
    {
        const uint4* A16 = (const uint4*)(Xg + (size_t)row0 * DDIM);
        const uint4* B16 = (const uint4*)(Yg + (size_t)col0 * DDIM);
        #pragma unroll
        for (int it = 0; it < 4; it++) {
            int f   = it * 256 + tid;        // 1024 chunks per tile
            int row = f >> 3;
            int c   = f & 7;
            uint32_t dst = (uint32_t)(row * 128 + ((c ^ (row & 7)) << 4));
            *(uint4*)(smem + SM_A + dst) = A16[row * 8 + c];
            *(uint4*)(smem + SM_B + dst) = B16[row * 8 + c];
        }
    }
    __syncthreads();

    float acc[2][8][4];
    #pragma unroll
    for (int mt = 0; mt < 2; mt++)
        #pragma unroll
        for (int nt = 0; nt < 8; nt++)
            #pragma unroll
            for (int r = 0; r < 4; r++) acc[mt][nt][r] = 0.0f;

    // 4 k-steps of k32 fp8. B-fragments consumed immediately to keep live
    // ranges short (2-CTA occupancy needs <=128 regs).
    #pragma unroll
    for (int ks = 0; ks < 4; ks++) {
        uint32_t a[2][4];
        #pragma unroll
        for (int mt = 0; mt < 2; mt++) {
            int r  = warp_m * 32 + mt * 16 + (lane & 15);
            int kb = ks * 32 + (lane >> 4) * 16;           // byte offset in row
            uint32_t addr = sb + SM_A + (uint32_t)(r * 128 + (((kb >> 4) ^ (r & 7)) << 4));
            ldmatrix_x4(a[mt], addr);
        }
        #pragma unroll
        for (int nt2 = 0; nt2 < 4; nt2++) {
            int r  = warp_n * 64 + nt2 * 16 + (lane & 7) + ((lane >> 4) << 3);
            int kb = ks * 32 + ((lane >> 3) & 1) * 16;
            uint32_t addr = sb + SM_B + (uint32_t)(r * 128 + (((kb >> 4) ^ (r & 7)) << 4));
            uint32_t t[4];
            ldmatrix_x4(t, addr);
            mma_fp8(acc[0][nt2*2],     a[0], &t[0]);
            mma_fp8(acc[0][nt2*2 + 1], a[0], &t[2]);
            mma_fp8(acc[1][nt2*2],     a[1], &t[0]);
            mma_fp8(acc[1][nt2*2 + 1], a[1], &t[2]);
        }
    }

    // Epilogue: fragment (mt,nt) reg r -> m = warp_m*32+mt*16+(lane/4)+(r>=2?8:0),
    //                                     n = warp_n*64+nt*8+(lane%4)*2+(r&1)
    const float* xns = (const float*)(smem + SM_XN);
    const float* yns = (const float*)(smem + SM_YN);
    float local = 0.0f;
    #pragma unroll
    for (int mt = 0; mt < 2; mt++) {
        int mbase = warp_m * 32 + mt * 16 + (lane >> 2);
        float xn0 = xns[mbase];
        float xn1 = xns[mbase + 8];
        #pragma unroll
        for (int nt = 0; nt < 8; nt++) {
            int nbase = warp_n * 64 + nt * 8 + (lane & 3) * 2;
            float yn0 = yns[nbase];
            float yn1 = yns[nbase + 1];
            float d2_00 = xn0 + yn0 - 2.0f * acc[mt][nt][0];
            float d2_01 = xn0 + yn1 - 2.0f * acc[mt][nt][1];
            float d2_10 = xn1 + yn0 - 2.0f * acc[mt][nt][2];
            float d2_11 = xn1 + yn1 - 2.0f * acc[mt][nt][3];
            if (p == 0) {
                local += fmaxf(d2_00, 1e-12f) + fmaxf(d2_01, 1e-12f)
                       + fmaxf(d2_10, 1e-12f) + fmaxf(d2_11, 1e-12f);
            } else {
                if (d2_00 < 4.0f) { float t = 2.0f - sqrtf(fmaxf(d2_00, 1e-12f)); local += t*t; }
                if (d2_01 < 4.0f) { float t = 2.0f - sqrtf(fmaxf(d2_01, 1e-12f)); local += t*t; }
                if (d2_10 < 4.0f) { float t = 2.0f - sqrtf(fmaxf(d2_10, 1e-12f)); local += t*t; }
                if (d2_11 < 4.0f) { float t = 2.0f - sqrtf(fmaxf(d2_11, 1e-12f)); local += t*t; }
            }
        }
    }

    // Reduce: warp -> block -> one double atomic; last CTA writes output.
    #pragma unroll
    for (int o = 16; o; o >>= 1) local += __shfl_xor_sync(0xffffffffu, local, o);
    __shared__ float red[8];
    if (lane == 0) red[w] = local;
    __syncthreads();
    if (tid == 0) {
        float v = red[0] + red[1] + red[2] + red[3]
                + red[4] + red[5] + red[6] + red[7];
        atomicAdd(&g_accum, (double)v);
        __threadfence();
        unsigned t = atomicAdd(&g_count, 1u);
        if (t == NCTA_DIST - 1) {
            double total = atomicAdd(&g_accum, 0.0);   // coherent read
            out[0] = (float)(total * (1.0 / DENOM));
        }
    }
}

extern "C" void kernel_launch(void* const* d_in, const int* in_sizes, int n_in,
                              void* d_out, int out_size) {
    const float* mu    = (const float*)d_in[0];
    const float* sigma = (const float*)d_in[1];
    const float* epsA  = (const float*)d_in[2];
    const float* epsB  = (const float*)d_in[3];
    const float* epsC  = (const float*)d_in[4];
    (void)in_sizes; (void)n_in; (void)out_size;

    cudaFuncSetAttribute(k_dist, cudaFuncAttributeMaxDynamicSharedMemorySize, SM_TOTAL);

    k_gen<<<(NROWS * 32) / 256, 256>>>(mu, sigma, epsA, epsB, epsC);
    dim3 grid(4, 4, 3 * NMC);
    k_dist<<<grid, 256, SM_TOTAL>>>((float*)d_out);
}

// round 6
// speedup vs baseline: 1.5746x; 1.0520x over previous
#include <cuda_runtime.h>
#include <cuda_bf16.h>
#include <math.h>
#include <stdint.h>

#define NPTS 512
#define DDIM 128
#define NMC  64
#define NROWS (3*NMC*NPTS)
#define DENOM 16777216.0
#define NTASK 3072
#define GRID  296

// Scratch (static device globals — no allocation allowed)
__device__ uint8_t g_Xf8[(size_t)3*NMC*NPTS*DDIM];   // 12.6MB e4m3
__device__ float   g_norm[3*NMC*NPTS];
__device__ double  g_accum;
__device__ unsigned g_count;

__device__ __forceinline__ uint32_t smem_u32(const void* p) {
    uint32_t a;
    asm("{ .reg .u64 t; cvta.to.shared.u64 t, %1; cvt.u32.u64 %0, t; }" : "=r"(a) : "l"(p));
    return a;
}

__device__ __forceinline__ void ldmatrix_x4(uint32_t* r, uint32_t addr) {
    asm volatile("ldmatrix.sync.aligned.m8n8.x4.shared.b16 {%0,%1,%2,%3}, [%4];"
                 : "=r"(r[0]), "=r"(r[1]), "=r"(r[2]), "=r"(r[3]) : "r"(addr));
}

__device__ __forceinline__ void mma_fp8(float* c, const uint32_t* a, const uint32_t* b) {
    asm volatile(
        "mma.sync.aligned.m16n8k32.row.col.f32.e4m3.e4m3.f32 "
        "{%0,%1,%2,%3}, {%4,%5,%6,%7}, {%8,%9}, {%0,%1,%2,%3};"
        : "+f"(c[0]), "+f"(c[1]), "+f"(c[2]), "+f"(c[3])
        : "r"(a[0]), "r"(a[1]), "r"(a[2]), "r"(a[3]), "r"(b[0]), "r"(b[1]));
}

__device__ __forceinline__ void cp16(uint32_t dst, const void* src) {
    asm volatile("cp.async.cg.shared.global [%0], [%1], 16;"
                 :: "r"(dst), "l"(__cvta_generic_to_global(src)) : "memory");
}
#define CP_COMMIT() asm volatile("cp.async.commit_group;" ::: "memory")
#define CP_WAIT1()  asm volatile("cp.async.wait_group 1;"  ::: "memory")

__device__ __forceinline__ uint32_t pack4_e4m3(float x0, float x1, float x2, float x3) {
    uint16_t lo, hi;
    asm("cvt.rn.satfinite.e4m3x2.f32 %0, %1, %2;" : "=h"(lo) : "f"(x1), "f"(x0));
    asm("cvt.rn.satfinite.e4m3x2.f32 %0, %1, %2;" : "=h"(hi) : "f"(x3), "f"(x2));
    return (uint32_t)lo | ((uint32_t)hi << 16);
}

// ---------------- k_gen: x = mu + sigma*eps -> e4m3 X, fp32 ||x||^2 ------
__global__ void k_gen(const float* __restrict__ mu, const float* __restrict__ sigma,
                      const float* __restrict__ epsA, const float* __restrict__ epsB,
                      const float* __restrict__ epsC) {
    if (blockIdx.x == 0 && threadIdx.x == 0) { g_accum = 0.0; g_count = 0u; }
    int w = (blockIdx.x * blockDim.x + threadIdx.x) >> 5;
    int lane = threadIdx.x & 31;
    if (w >= NROWS) return;
    int s   = w / (NMC*NPTS);
    int rem = w - s*(NMC*NPTS);
    int m   = rem / NPTS;
    int n   = rem - m*NPTS;
    const float* eps = (s == 0) ? epsA : (s == 1) ? epsB : epsC;
    float4 a = ((const float4*)(mu    + (size_t)(s*NPTS + n)*DDIM))[lane];
    float4 b = ((const float4*)(sigma + (size_t)(s*NPTS + n)*DDIM))[lane];
    float4 e = ((const float4*)(eps   + ((size_t)m*NPTS + n)*DDIM))[lane];
    float4 x;
    x.x = fmaf(b.x, e.x, a.x);
    x.y = fmaf(b.y, e.y, a.y);
    x.z = fmaf(b.z, e.z, a.z);
    x.w = fmaf(b.w, e.w, a.w);
    ((uint32_t*)(g_Xf8 + (size_t)w*DDIM))[lane] = pack4_e4m3(x.x, x.y, x.z, x.w);
    float ss = x.x*x.x + x.y*x.y + x.z*x.z + x.w*x.w;
    #pragma unroll
    for (int o = 16; o; o >>= 1) ss += __shfl_xor_sync(0xffffffffu, ss, o);
    if (lane == 0) g_norm[w] = ss;
}

// Per-buffer layout: A[0:16384) B[16384:32768) xn[32768:33280) yn[33280:33792)
#define BUFSZ 33792
#define SM_TOTAL (2*BUFSZ)

// Task decode: p fastest, then m, bx, by. 3*64*4*4 = 3072.
__device__ __forceinline__ void prefetch_task(int t, uint32_t sbuf, int tid) {
    int p  = t % 3;  int r1 = t / 3;
    int m  = r1 & 63; int r2 = r1 >> 6;
    int bx = r2 & 3;  int by = r2 >> 2;
    int rs = (p == 0) ? 0 : 1;
    int cs = (p == 0) ? 2 : ((p == 1) ? 0 : 2);
    const uint8_t* Xg = g_Xf8 + ((size_t)(rs*NMC + m)*NPTS + by*128) * DDIM;
    const uint8_t* Yg = g_Xf8 + ((size_t)(cs*NMC + m)*NPTS + bx*128) * DDIM;
    #pragma unroll
    for (int i2 = 0; i2 < 4; i2++) {
        int f = i2 * 256 + tid;               // 1024 chunks per tile
        int row = f >> 3, c = f & 7;
        uint32_t dsto = (uint32_t)(row * 128 + ((c ^ (row & 7)) << 4));
        const uint8_t* srcX = Xg + row * DDIM + c * 16;
        const uint8_t* srcY = Yg + row * DDIM + c * 16;
        cp16(sbuf + dsto, srcX);
        cp16(sbuf + 16384u + dsto, srcY);
    }
    if (tid < 32) {
        const float* nX = g_norm + (size_t)(rs*NMC + m)*NPTS + by*128;
        cp16(sbuf + 32768u + tid*16, nX + tid*4);
    } else if (tid < 64) {
        const float* nY = g_norm + (size_t)(cs*NMC + m)*NPTS + bx*128;
        cp16(sbuf + 33280u + (tid-32)*16, nY + (tid-32)*4);
    }
}

// Persistent fp8 warp-MMA Gram GEMM, double-buffered cp.async pipeline.
__global__ __launch_bounds__(256, 2) void k_dist(float* __restrict__ out) {
    extern __shared__ char smem[];
    uint32_t sb = smem_u32(smem);
    int tid  = threadIdx.x;
    int lane = tid & 31;
    int w    = tid >> 5;
    int warp_m = w & 3;     // 4 warps over M (32 rows each)
    int warp_n = w >> 2;    // 2 warps over N (64 cols each)

    float local = 0.0f;

    // Prologue: prefetch first task into buffer 0.
    prefetch_task((int)blockIdx.x, sb, tid);
    CP_COMMIT();

    int it = 0;
    for (int t = (int)blockIdx.x; t < NTASK; t += GRID, it ^= 1) {
        int nxt = t + GRID;
        if (nxt < NTASK) prefetch_task(nxt, sb + (uint32_t)(it ^ 1) * BUFSZ, tid);
        CP_COMMIT();
        CP_WAIT1();          // current task's data resident
        __syncthreads();

        uint32_t bufA = sb + (uint32_t)it * BUFSZ;
        uint32_t bufB = bufA + 16384u;
        const float* xns = (const float*)(smem + it * BUFSZ + 32768);
        const float* yns = (const float*)(smem + it * BUFSZ + 33280);
        int p = t % 3;

        float acc[2][8][4];
        #pragma unroll
        for (int mt = 0; mt < 2; mt++)
            #pragma unroll
            for (int nt = 0; nt < 8; nt++)
                #pragma unroll
                for (int r = 0; r < 4; r++) acc[mt][nt][r] = 0.0f;

        #pragma unroll
        for (int ks = 0; ks < 4; ks++) {
            uint32_t a[2][4];
            #pragma unroll
            for (int mt = 0; mt < 2; mt++) {
                int r  = warp_m * 32 + mt * 16 + (lane & 15);
                int kb = ks * 32 + (lane >> 4) * 16;
                uint32_t addr = bufA + (uint32_t)(r * 128 + (((kb >> 4) ^ (r & 7)) << 4));
                ldmatrix_x4(a[mt], addr);
            }
            #pragma unroll
            for (int nt2 = 0; nt2 < 4; nt2++) {
                int r  = warp_n * 64 + nt2 * 16 + (lane & 7) + ((lane >> 4) << 3);
                int kb = ks * 32 + ((lane >> 3) & 1) * 16;
                uint32_t addr = bufB + (uint32_t)(r * 128 + (((kb >> 4) ^ (r & 7)) << 4));
                uint32_t tb[4];
                ldmatrix_x4(tb, addr);
                mma_fp8(acc[0][nt2*2],     a[0], &tb[0]);
                mma_fp8(acc[0][nt2*2 + 1], a[0], &tb[2]);
                mma_fp8(acc[1][nt2*2],     a[1], &tb[0]);
                mma_fp8(acc[1][nt2*2 + 1], a[1], &tb[2]);
            }
        }

        // Fused epilogue; accumulate into 'local' across tasks.
        #pragma unroll
        for (int mt = 0; mt < 2; mt++) {
            int mbase = warp_m * 32 + mt * 16 + (lane >> 2);
            float xn0 = xns[mbase];
            float xn1 = xns[mbase + 8];
            #pragma unroll
            for (int nt = 0; nt < 8; nt++) {
                int nbase = warp_n * 64 + nt * 8 + (lane & 3) * 2;
                float yn0 = yns[nbase];
                float yn1 = yns[nbase + 1];
                float d2_00 = xn0 + yn0 - 2.0f * acc[mt][nt][0];
                float d2_01 = xn0 + yn1 - 2.0f * acc[mt][nt][1];
                float d2_10 = xn1 + yn0 - 2.0f * acc[mt][nt][2];
                float d2_11 = xn1 + yn1 - 2.0f * acc[mt][nt][3];
                if (p == 0) {
                    local += fmaxf(d2_00, 1e-12f) + fmaxf(d2_01, 1e-12f)
                           + fmaxf(d2_10, 1e-12f) + fmaxf(d2_11, 1e-12f);
                } else {
                    if (d2_00 < 4.0f) { float q = 2.0f - sqrtf(fmaxf(d2_00, 1e-12f)); local += q*q; }
                    if (d2_01 < 4.0f) { float q = 2.0f - sqrtf(fmaxf(d2_01, 1e-12f)); local += q*q; }
                    if (d2_10 < 4.0f) { float q = 2.0f - sqrtf(fmaxf(d2_10, 1e-12f)); local += q*q; }
                    if (d2_11 < 4.0f) { float q = 2.0f - sqrtf(fmaxf(d2_11, 1e-12f)); local += q*q; }
                }
            }
        }
        __syncthreads();   // all warps done with this buffer before it is refilled
    }

    // Reduce: warp -> block -> one double atomic; last CTA writes output.
    #pragma unroll
    for (int o = 16; o; o >>= 1) local += __shfl_xor_sync(0xffffffffu, local, o);
    __shared__ float red[8];
    if (lane == 0) red[w] = local;
    __syncthreads();
    if (tid == 0) {
        float v = red[0] + red[1] + red[2] + red[3]
                + red[4] + red[5] + red[6] + red[7];
        atomicAdd(&g_accum, (double)v);
        __threadfence();
        unsigned c = atomicAdd(&g_count, 1u);
        if (c == GRID - 1) {
            double total = atomicAdd(&g_accum, 0.0);   // coherent read
            out[0] = (float)(total * (1.0 / DENOM));
        }
    }
}

extern "C" void kernel_launch(void* const* d_in, const int* in_sizes, int n_in,
                              void* d_out, int out_size) {
    const float* mu    = (const float*)d_in[0];
    const float* sigma = (const float*)d_in[1];
    const float* epsA  = (const float*)d_in[2];
    const float* epsB  = (const float*)d_in[3];
    const float* epsC  = (const float*)d_in[4];
    (void)in_sizes; (void)n_in; (void)out_size;

    cudaFuncSetAttribute(k_dist, cudaFuncAttributeMaxDynamicSharedMemorySize, SM_TOTAL);

    k_gen<<<(NROWS * 32) / 256, 256>>>(mu, sigma, epsA, epsB, epsC);
    k_dist<<<GRID, 256, SM_TOTAL>>>((float*)d_out);
}

// round 7
// speedup vs baseline: 1.9583x; 1.2437x over previous
#include <cuda_runtime.h>
#include <cuda_bf16.h>
#include <math.h>
#include <stdint.h>

#define NPTS 512
#define DDIM 128
#define NMC  64
#define DENOM 16777216.0
#define NTASK 2048
#define GRID  296

// Scratch (static device globals — no allocation allowed)
__device__ uint8_t g_Xf8[(size_t)3*NMC*NPTS*DDIM];   // 12.6MB e4m3
__device__ float   g_norm[3*NMC*NPTS];
__device__ float   g_part[2*NMC*64*DDIM];            // per-block row-sum partials, sets A/C
__device__ double  g_accum;
__device__ unsigned g_count;

__device__ __forceinline__ uint32_t smem_u32(const void* p) {
    uint32_t a;
    asm("{ .reg .u64 t; cvta.to.shared.u64 t, %1; cvt.u32.u64 %0, t; }" : "=r"(a) : "l"(p));
    return a;
}

__device__ __forceinline__ void ldmatrix_x4(uint32_t* r, uint32_t addr) {
    asm volatile("ldmatrix.sync.aligned.m8n8.x4.shared.b16 {%0,%1,%2,%3}, [%4];"
                 : "=r"(r[0]), "=r"(r[1]), "=r"(r[2]), "=r"(r[3]) : "r"(addr));
}

__device__ __forceinline__ void mma_fp8(float* c, const uint32_t* a, const uint32_t* b) {
    asm volatile(
        "mma.sync.aligned.m16n8k32.row.col.f32.e4m3.e4m3.f32 "
        "{%0,%1,%2,%3}, {%4,%5,%6,%7}, {%8,%9}, {%0,%1,%2,%3};"
        : "+f"(c[0]), "+f"(c[1]), "+f"(c[2]), "+f"(c[3])
        : "r"(a[0]), "r"(a[1]), "r"(a[2]), "r"(a[3]), "r"(b[0]), "r"(b[1]));
}

__device__ __forceinline__ void cp16(uint32_t dst, const void* src) {
    asm volatile("cp.async.cg.shared.global [%0], [%1], 16;"
                 :: "r"(dst), "l"(__cvta_generic_to_global(src)) : "memory");
}
#define CP_COMMIT() asm volatile("cp.async.commit_group;" ::: "memory")
#define CP_WAIT1()  asm volatile("cp.async.wait_group 1;"  ::: "memory")

__device__ __forceinline__ uint32_t pack4_e4m3(float x0, float x1, float x2, float x3) {
    uint16_t lo, hi;
    asm("cvt.rn.satfinite.e4m3x2.f32 %0, %1, %2;" : "=h"(lo) : "f"(x1), "f"(x0));
    asm("cvt.rn.satfinite.e4m3x2.f32 %0, %1, %2;" : "=h"(hi) : "f"(x3), "f"(x2));
    return (uint32_t)lo | ((uint32_t)hi << 16);
}

// ---- k_gen: x = mu + sigma*eps -> e4m3 X, fp32 norms, A/C row-sum partials.
// Block = 8 warps = 8 rows of one (s, m). Grid = 3*64*64.
__global__ __launch_bounds__(256) void k_gen(
        const float* __restrict__ mu, const float* __restrict__ sigma,
        const float* __restrict__ epsA, const float* __restrict__ epsB,
        const float* __restrict__ epsC) {
    if (blockIdx.x == 0 && threadIdx.x == 0) { g_accum = 0.0; g_count = 0u; }
    int b  = blockIdx.x;
    int s  = b / (NMC * 64);
    int m  = (b / 64) % NMC;
    int ng = b % 64;
    int tid  = threadIdx.x;
    int wid  = tid >> 5;
    int lane = tid & 31;
    int n = ng * 8 + wid;

    const float* eps = (s == 0) ? epsA : (s == 1) ? epsB : epsC;
    float4 a = ((const float4*)(mu    + (size_t)(s*NPTS + n)*DDIM))[lane];
    float4 g = ((const float4*)(sigma + (size_t)(s*NPTS + n)*DDIM))[lane];
    float4 e = ((const float4*)(eps   + ((size_t)m*NPTS + n)*DDIM))[lane];
    float4 x;
    x.x = fmaf(g.x, e.x, a.x);
    x.y = fmaf(g.y, e.y, a.y);
    x.z = fmaf(g.z, e.z, a.z);
    x.w = fmaf(g.w, e.w, a.w);
    size_t row = (size_t)(s*NMC + m)*NPTS + n;
    ((uint32_t*)(g_Xf8 + row*DDIM))[lane] = pack4_e4m3(x.x, x.y, x.z, x.w);
    float ss = x.x*x.x + x.y*x.y + x.z*x.z + x.w*x.w;
    #pragma unroll
    for (int o = 16; o; o >>= 1) ss += __shfl_xor_sync(0xffffffffu, ss, o);
    if (lane == 0) g_norm[row] = ss;

    if (s != 1) {   // partial row-sum vectors for the analytic pos term
        __shared__ float sx[8 * DDIM];
        ((float4*)sx)[wid * 32 + lane] = x;
        __syncthreads();
        if (tid < DDIM) {
            float acc = 0.0f;
            #pragma unroll
            for (int ww = 0; ww < 8; ww++) acc += sx[ww * DDIM + tid];
            int si = (s == 0) ? 0 : 1;
            g_part[((si*NMC + m)*64 + ng)*DDIM + tid] = acc;
        }
    }
}

// ---- k_pos: exact positive term, one block per m ----
__global__ __launch_bounds__(256) void k_pos() {
    int m = blockIdx.x;
    int tid = threadIdx.x;
    float dot = 0.0f;
    if (tid < DDIM) {
        float sa = 0.0f, sc = 0.0f;
        for (int ng = 0; ng < 64; ng++) {
            sa += g_part[((0*NMC + m)*64 + ng)*DDIM + tid];
            sc += g_part[((1*NMC + m)*64 + ng)*DDIM + tid];
        }
        dot = sa * sc;
    }
    float ns = 0.0f;
    for (int i = tid; i < NPTS; i += 256) {
        ns += g_norm[(size_t)(0*NMC + m)*NPTS + i]
            + g_norm[(size_t)(2*NMC + m)*NPTS + i];
    }
    float u = 512.0f * ns - 2.0f * dot;
    #pragma unroll
    for (int o = 16; o; o >>= 1) u += __shfl_xor_sync(0xffffffffu, u, o);
    __shared__ float red[8];
    if ((tid & 31) == 0) red[tid >> 5] = u;
    __syncthreads();
    if (tid == 0) {
        float v = red[0] + red[1] + red[2] + red[3]
                + red[4] + red[5] + red[6] + red[7];
        atomicAdd(&g_accum, (double)v);
    }
}

// Per-buffer layout: A[0:16384) B[16384:32768) xn[32768:33280) yn[33280:33792)
#define BUFSZ 33792
#define SM_TOTAL (2*BUFSZ)

// Neg tasks only: t bit0 -> pair (0=dBA cs=0, 1=dBC cs=2); rows always set B.
__device__ __forceinline__ void prefetch_task(int t, uint32_t sbuf, int tid) {
    int pp = t & 1;  int r1 = t >> 1;
    int m  = r1 & 63; int r2 = r1 >> 6;
    int bx = r2 & 3;  int by = r2 >> 2;
    int cs = pp ? 2 : 0;
    const uint8_t* Xg = g_Xf8 + ((size_t)(1*NMC + m)*NPTS + by*128) * DDIM;
    const uint8_t* Yg = g_Xf8 + ((size_t)(cs*NMC + m)*NPTS + bx*128) * DDIM;
    #pragma unroll
    for (int i2 = 0; i2 < 4; i2++) {
        int f = i2 * 256 + tid;               // 1024 chunks per tile
        int row = f >> 3, c = f & 7;
        uint32_t dsto = (uint32_t)(row * 128 + ((c ^ (row & 7)) << 4));
        cp16(sbuf + dsto, Xg + row * DDIM + c * 16);
        cp16(sbuf + 16384u + dsto, Yg + row * DDIM + c * 16);
    }
    if (tid < 32) {
        const float* nX = g_norm + (size_t)(1*NMC + m)*NPTS + by*128;
        cp16(sbuf + 32768u + tid*16, nX + tid*4);
    } else if (tid < 64) {
        const float* nY = g_norm + (size_t)(cs*NMC + m)*NPTS + bx*128;
        cp16(sbuf + 33280u + (tid-32)*16, nY + (tid-32)*4);
    }
}

// Persistent fp8 warp-MMA Gram GEMM, neg terms only, double-buffered.
__global__ __launch_bounds__(256, 2) void k_dist(float* __restrict__ out) {
    extern __shared__ char smem[];
    uint32_t sb = smem_u32(smem);
    int tid  = threadIdx.x;
    int lane = tid & 31;
    int w    = tid >> 5;
    int warp_m = w & 3;     // 4 warps over M (32 rows each)
    int warp_n = w >> 2;    // 2 warps over N (64 cols each)

    float local = 0.0f;

    prefetch_task((int)blockIdx.x, sb, tid);
    CP_COMMIT();

    int it = 0;
    for (int t = (int)blockIdx.x; t < NTASK; t += GRID, it ^= 1) {
        int nxt = t + GRID;
        if (nxt < NTASK) prefetch_task(nxt, sb + (uint32_t)(it ^ 1) * BUFSZ, tid);
        CP_COMMIT();
        CP_WAIT1();
        __syncthreads();

        uint32_t bufA = sb + (uint32_t)it * BUFSZ;
        uint32_t bufB = bufA + 16384u;
        const float* xns = (const float*)(smem + it * BUFSZ + 32768);
        const float* yns = (const float*)(smem + it * BUFSZ + 33280);

        float acc[2][8][4];
        #pragma unroll
        for (int mt = 0; mt < 2; mt++)
            #pragma unroll
            for (int nt = 0; nt < 8; nt++)
                #pragma unroll
                for (int r = 0; r < 4; r++) acc[mt][nt][r] = 0.0f;

        #pragma unroll
        for (int ks = 0; ks < 4; ks++) {
            uint32_t a[2][4];
            #pragma unroll
            for (int mt = 0; mt < 2; mt++) {
                int r  = warp_m * 32 + mt * 16 + (lane & 15);
                int kb = ks * 32 + (lane >> 4) * 16;
                uint32_t addr = bufA + (uint32_t)(r * 128 + (((kb >> 4) ^ (r & 7)) << 4));
                ldmatrix_x4(a[mt], addr);
            }
            #pragma unroll
            for (int nt2 = 0; nt2 < 4; nt2++) {
                int r  = warp_n * 64 + nt2 * 16 + (lane & 7) + ((lane >> 4) << 3);
                int kb = ks * 32 + ((lane >> 3) & 1) * 16;
                uint32_t addr = bufB + (uint32_t)(r * 128 + (((kb >> 4) ^ (r & 7)) << 4));
                uint32_t tb[4];
                ldmatrix_x4(tb, addr);
                mma_fp8(acc[0][nt2*2],     a[0], &tb[0]);
                mma_fp8(acc[0][nt2*2 + 1], a[0], &tb[2]);
                mma_fp8(acc[1][nt2*2],     a[1], &tb[0]);
                mma_fp8(acc[1][nt2*2 + 1], a[1], &tb[2]);
            }
        }

        // Neg-only epilogue: relu(2-d)>0 iff d2<4 iff acc > px+py,
        // px = 0.5*xn-1, py = 0.5*yn-1; d2 = 2*((px+py)-acc)+4.
        float py[8][2];
        #pragma unroll
        for (int nt = 0; nt < 8; nt++) {
            int nbase = warp_n * 64 + nt * 8 + (lane & 3) * 2;
            py[nt][0] = fmaf(yns[nbase],     0.5f, -1.0f);
            py[nt][1] = fmaf(yns[nbase + 1], 0.5f, -1.0f);
        }
        #pragma unroll
        for (int mt = 0; mt < 2; mt++) {
            int mbase = warp_m * 32 + mt * 16 + (lane >> 2);
            float px0 = fmaf(xns[mbase],     0.5f, -1.0f);
            float px1 = fmaf(xns[mbase + 8], 0.5f, -1.0f);
            #pragma unroll
            for (int nt = 0; nt < 8; nt++) {
                float t00 = px0 + py[nt][0];
                float t01 = px0 + py[nt][1];
                float t10 = px1 + py[nt][0];
                float t11 = px1 + py[nt][1];
                if (acc[mt][nt][0] > t00) { float d2 = 2.0f*(t00 - acc[mt][nt][0]) + 4.0f; float q = 2.0f - sqrtf(fmaxf(d2, 1e-12f)); local += q*q; }
                if (acc[mt][nt][1] > t01) { float d2 = 2.0f*(t01 - acc[mt][nt][1]) + 4.0f; float q = 2.0f - sqrtf(fmaxf(d2, 1e-12f)); local += q*q; }
                if (acc[mt][nt][2] > t10) { float d2 = 2.0f*(t10 - acc[mt][nt][2]) + 4.0f; float q = 2.0f - sqrtf(fmaxf(d2, 1e-12f)); local += q*q; }
                if (acc[mt][nt][3] > t11) { float d2 = 2.0f*(t11 - acc[mt][nt][3]) + 4.0f; float q = 2.0f - sqrtf(fmaxf(d2, 1e-12f)); local += q*q; }
            }
        }
        __syncthreads();
    }

    #pragma unroll
    for (int o = 16; o; o >>= 1) local += __shfl_xor_sync(0xffffffffu, local, o);
    __shared__ float red[8];
    if (lane == 0) red[w] = local;
    __syncthreads();
    if (tid == 0) {
        float v = red[0] + red[1] + red[2] + red[3]
                + red[4] + red[5] + red[6] + red[7];
        atomicAdd(&g_accum, (double)v);
        __threadfence();
        unsigned c = atomicAdd(&g_count, 1u);
        if (c == GRID - 1) {
            double total = atomicAdd(&g_accum, 0.0);
            out[0] = (float)(total * (1.0 / DENOM));
        }
    }
}

extern "C" void kernel_launch(void* const* d_in, const int* in_sizes, int n_in,
                              void* d_out, int out_size) {
    const float* mu    = (const float*)d_in[0];
    const float* sigma = (const float*)d_in[1];
    const float* epsA  = (const float*)d_in[2];
    const float* epsB  = (const float*)d_in[3];
    const float* epsC  = (const float*)d_in[4];
    (void)in_sizes; (void)n_in; (void)out_size;

    cudaFuncSetAttribute(k_dist, cudaFuncAttributeMaxDynamicSharedMemorySize, SM_TOTAL);

    k_gen<<<3*NMC*64, 256>>>(mu, sigma, epsA, epsB, epsC);
    k_pos<<<NMC, 256>>>();
    k_dist<<<GRID, 256, SM_TOTAL>>>((float*)d_out);
}